// round 1
// baseline (speedup 1.0000x reference)
#include <cuda_runtime.h>
#include <math.h>

#define N_TOK  4096
#define EMBED  768
#define NHEAD  12
#define DHEAD  64
#define KPATCH 256
#define QKVOUT (3*EMBED)

// ---- device scratch (allocation-free: module globals) ----
__device__ float g_tok[N_TOK * EMBED];                 // post patch-embed / post-LN tokens
__device__ float g_q[NHEAD * N_TOK * DHEAD];           // [h, n, d]
__device__ float g_k[NHEAD * N_TOK * DHEAD];
__device__ float g_v[NHEAD * N_TOK * DHEAD];

// ============================================================
// Kernel 1: patch-embed GEMM.  out[m,n] = sum_k patch[m,k]*W[n,k] + b[n]
// M=4096 tokens, N=768, K=256.  64x64x16 tile, 256 thr, 4x4 microtile.
// patch[m,k] gathered from image: m=(pr,pc), k=(i,j) -> x[pr*16+i][pc*16+j]
// ============================================================
__global__ __launch_bounds__(256) void patch_embed_kernel(
    const float* __restrict__ x, const float* __restrict__ w,
    const float* __restrict__ bias)
{
    __shared__ float As[16][64];
    __shared__ float Bs[16][64];
    const int tid = threadIdx.x;
    const int tx = tid & 15, ty = tid >> 4;
    const int m0 = blockIdx.y * 64;
    const int n0 = blockIdx.x * 64;

    const int lm = tid >> 2;          // 0..63 row within tile (load)
    const int lk = (tid & 3) * 4;     // 0,4,8,12 k offset (load)

    const int tok = m0 + lm;
    const int pr = tok >> 6, pc = tok & 63;

    float acc[4][4];
#pragma unroll
    for (int i = 0; i < 4; i++)
#pragma unroll
        for (int j = 0; j < 4; j++) acc[i][j] = 0.f;

    for (int kt = 0; kt < KPATCH; kt += 16) {
        // A tile: patch[tok][kt+lk .. kt+lk+3]  (contiguous in image row)
        const int i = (kt + lk) >> 4;      // pixel row within patch
        const int j = lk;                  // pixel col within patch (kt%16==0)
        float4 a4 = *(const float4*)&x[(pr * 16 + i) * 1024 + pc * 16 + j];
        As[lk + 0][lm] = a4.x; As[lk + 1][lm] = a4.y;
        As[lk + 2][lm] = a4.z; As[lk + 3][lm] = a4.w;
        // B tile: W[n0+lm][kt+lk .. +3]
        float4 b4 = *(const float4*)&w[(n0 + lm) * KPATCH + kt + lk];
        Bs[lk + 0][lm] = b4.x; Bs[lk + 1][lm] = b4.y;
        Bs[lk + 2][lm] = b4.z; Bs[lk + 3][lm] = b4.w;
        __syncthreads();
#pragma unroll
        for (int kk = 0; kk < 16; kk++) {
            float4 av = *(const float4*)&As[kk][ty * 4];
            float4 bv = *(const float4*)&Bs[kk][tx * 4];
            float am[4] = {av.x, av.y, av.z, av.w};
            float bn[4] = {bv.x, bv.y, bv.z, bv.w};
#pragma unroll
            for (int i2 = 0; i2 < 4; i2++)
#pragma unroll
                for (int j2 = 0; j2 < 4; j2++) acc[i2][j2] += am[i2] * bn[j2];
        }
        __syncthreads();
    }
#pragma unroll
    for (int i = 0; i < 4; i++) {
        int m = m0 + ty * 4 + i;
#pragma unroll
        for (int j = 0; j < 4; j++) {
            int n = n0 + tx * 4 + j;
            g_tok[m * EMBED + n] = acc[i][j] + bias[n];
        }
    }
}

// ============================================================
// Kernel 2: LayerNorm per token (two-pass), 256 threads, E=768 -> 3/thread
// ============================================================
__device__ __forceinline__ float block_sum256(float v) {
    __shared__ float sh[8];
    __syncthreads();
    const int lane = threadIdx.x & 31, wrp = threadIdx.x >> 5;
#pragma unroll
    for (int o = 16; o > 0; o >>= 1) v += __shfl_xor_sync(0xffffffffu, v, o);
    if (lane == 0) sh[wrp] = v;
    __syncthreads();
    if (wrp == 0) {
        v = (lane < 8) ? sh[lane] : 0.f;
#pragma unroll
        for (int o = 4; o > 0; o >>= 1) v += __shfl_xor_sync(0xffffffffu, v, o);
        if (lane == 0) sh[0] = v;
    }
    __syncthreads();
    return sh[0];
}

__global__ __launch_bounds__(256) void ln_kernel(
    const float* __restrict__ gamma, const float* __restrict__ beta)
{
    const int n = blockIdx.x;
    const int t = threadIdx.x;
    float* row = &g_tok[n * EMBED];
    float v0 = row[t], v1 = row[t + 256], v2 = row[t + 512];
    float total = block_sum256(v0 + v1 + v2);
    float mu = total * (1.f / EMBED);
    float d0 = v0 - mu, d1 = v1 - mu, d2 = v2 - mu;
    float tot2 = block_sum256(d0 * d0 + d1 * d1 + d2 * d2);
    float inv = rsqrtf(tot2 * (1.f / EMBED) + 1e-6f);
    row[t]       = d0 * inv * gamma[t]       + beta[t];
    row[t + 256] = d1 * inv * gamma[t + 256] + beta[t + 256];
    row[t + 512] = d2 * inv * gamma[t + 512] + beta[t + 512];
}

// ============================================================
// Kernel 3: QKV GEMM.  out[m,c] = sum_k tok[m,k]*Wq[c,k]
// M=4096, N=2304, K=768. Same tiling. Epilogue scatters to q/k/v [h,n,d].
// ============================================================
__global__ __launch_bounds__(256) void qkv_kernel(const float* __restrict__ w)
{
    __shared__ float As[16][64];
    __shared__ float Bs[16][64];
    const int tid = threadIdx.x;
    const int tx = tid & 15, ty = tid >> 4;
    const int m0 = blockIdx.y * 64;
    const int n0 = blockIdx.x * 64;
    const int lm = tid >> 2;
    const int lk = (tid & 3) * 4;

    float acc[4][4];
#pragma unroll
    for (int i = 0; i < 4; i++)
#pragma unroll
        for (int j = 0; j < 4; j++) acc[i][j] = 0.f;

    for (int kt = 0; kt < EMBED; kt += 16) {
        float4 a4 = *(const float4*)&g_tok[(m0 + lm) * EMBED + kt + lk];
        As[lk + 0][lm] = a4.x; As[lk + 1][lm] = a4.y;
        As[lk + 2][lm] = a4.z; As[lk + 3][lm] = a4.w;
        float4 b4 = *(const float4*)&w[(n0 + lm) * EMBED + kt + lk];
        Bs[lk + 0][lm] = b4.x; Bs[lk + 1][lm] = b4.y;
        Bs[lk + 2][lm] = b4.z; Bs[lk + 3][lm] = b4.w;
        __syncthreads();
#pragma unroll
        for (int kk = 0; kk < 16; kk++) {
            float4 av = *(const float4*)&As[kk][ty * 4];
            float4 bv = *(const float4*)&Bs[kk][tx * 4];
            float am[4] = {av.x, av.y, av.z, av.w};
            float bn[4] = {bv.x, bv.y, bv.z, bv.w};
#pragma unroll
            for (int i2 = 0; i2 < 4; i2++)
#pragma unroll
                for (int j2 = 0; j2 < 4; j2++) acc[i2][j2] += am[i2] * bn[j2];
        }
        __syncthreads();
    }
    // scatter: c = s*768 + h*64 + dd  (block of 4 cols never crosses a 64-boundary)
    const int c0 = n0 + tx * 4;
    const int s  = c0 / EMBED;
    const int r  = c0 % EMBED;
    const int h  = r / DHEAD;
    const int dd = r % DHEAD;
    float* dst = (s == 0) ? g_q : ((s == 1) ? g_k : g_v);
#pragma unroll
    for (int i = 0; i < 4; i++) {
        int m = m0 + ty * 4 + i;
        float* p = &dst[(h * N_TOK + m) * DHEAD + dd];
#pragma unroll
        for (int j = 0; j < 4; j++) p[j] = acc[i][j];
    }
}

// ============================================================
// Kernel 4: flash attention. block = (1 head, 64 queries), 64 threads,
// 1 query/thread. Online softmax with rare-rescale.  scale = 1/sqrt(64)
// ============================================================
__global__ __launch_bounds__(64) void attn_kernel(float* __restrict__ out)
{
    __shared__ float4 Ks[64 * 16];   // [64 keys][64 floats]
    __shared__ float4 Vs[64 * 16];
    const int h   = blockIdx.y;
    const int tid = threadIdx.x;
    const int q   = blockIdx.x * 64 + tid;

    const float4* Qg = (const float4*)&g_q[(h * N_TOK + q) * DHEAD];
    float4 q4[16];
#pragma unroll
    for (int i = 0; i < 16; i++) q4[i] = Qg[i];

    float4 o4[16];
#pragma unroll
    for (int i = 0; i < 16; i++) o4[i] = make_float4(0.f, 0.f, 0.f, 0.f);
    float m = -1e30f, l = 0.f;

    const float4* Kg = (const float4*)&g_k[h * N_TOK * DHEAD];
    const float4* Vg = (const float4*)&g_v[h * N_TOK * DHEAD];

    for (int t0 = 0; t0 < N_TOK; t0 += 64) {
        __syncthreads();
        const int base = t0 * 16;     // float4 index of tile start
#pragma unroll
        for (int i = 0; i < 16; i++) {
            Ks[i * 64 + tid] = Kg[base + i * 64 + tid];
            Vs[i * 64 + tid] = Vg[base + i * 64 + tid];
        }
        __syncthreads();

        for (int kk = 0; kk < 64; kk++) {
            const float4* kr = &Ks[kk * 16];
            float s = 0.f;
#pragma unroll
            for (int i = 0; i < 16; i++) {
                float4 kv = kr[i];
                s += q4[i].x * kv.x + q4[i].y * kv.y
                   + q4[i].z * kv.z + q4[i].w * kv.w;
            }
            s *= 0.125f;
            if (s > m) {               // rare (~log N times per row)
                float corr = __expf(m - s);
                l *= corr;
#pragma unroll
                for (int i = 0; i < 16; i++) {
                    o4[i].x *= corr; o4[i].y *= corr;
                    o4[i].z *= corr; o4[i].w *= corr;
                }
                m = s;
            }
            float p = __expf(s - m);
            l += p;
            const float4* vr = &Vs[kk * 16];
#pragma unroll
            for (int i = 0; i < 16; i++) {
                float4 vv = vr[i];
                o4[i].x += p * vv.x; o4[i].y += p * vv.y;
                o4[i].z += p * vv.z; o4[i].w += p * vv.w;
            }
        }
    }

    const float inv = 1.f / l;
    float4* op = (float4*)&out[q * EMBED + h * DHEAD];
#pragma unroll
    for (int i = 0; i < 16; i++) {
        op[i] = make_float4(o4[i].x * inv, o4[i].y * inv,
                            o4[i].z * inv, o4[i].w * inv);
    }
}

// ============================================================
extern "C" void kernel_launch(void* const* d_in, const int* in_sizes, int n_in,
                              void* d_out, int out_size)
{
    const float* x  = (const float*)d_in[0];
    const float* pw = (const float*)d_in[1];
    const float* pb = (const float*)d_in[2];
    const float* lg = (const float*)d_in[3];
    const float* lb = (const float*)d_in[4];
    const float* qw = (const float*)d_in[5];
    float* out = (float*)d_out;

    patch_embed_kernel<<<dim3(EMBED / 64, N_TOK / 64), 256>>>(x, pw, pb);
    ln_kernel<<<N_TOK, 256>>>(lg, lb);
    qkv_kernel<<<dim3(QKVOUT / 64, N_TOK / 64), 256>>>(qw);
    attn_kernel<<<dim3(N_TOK / 64, NHEAD), 64>>>(out);
}

// round 4
// speedup vs baseline: 4.4849x; 4.4849x over previous
#include <cuda_runtime.h>
#include <cstdint>
#include <math.h>

#define N_TOK  4096
#define EMBED  768
#define NHEAD  12
#define DHEAD  64
#define KPATCH 256

// ---- device scratch (allocation-free: module globals) ----
__device__ float g_tok[N_TOK * EMBED];
__device__ float g_q[NHEAD * N_TOK * DHEAD];   // [h, n, d]
__device__ float g_k[NHEAD * N_TOK * DHEAD];
__device__ float g_v[NHEAD * N_TOK * DHEAD];

// ============================================================
// helpers
// ============================================================
__device__ __forceinline__ uint32_t smem_u32(const void* p) {
    uint32_t a;
    asm("{ .reg .u64 t; cvta.to.shared.u64 t, %1; cvt.u32.u64 %0, t; }"
        : "=r"(a) : "l"(p));
    return a;
}
__device__ __forceinline__ void cp16(uint32_t dst, const void* src) {
    asm volatile("cp.async.cg.shared.global [%0], [%1], 16;"
                 :: "r"(dst), "l"(src));
}
#define CP_COMMIT() asm volatile("cp.async.commit_group;" ::: "memory")
#define CP_WAIT1()  asm volatile("cp.async.wait_group 1;" ::: "memory")

__device__ __forceinline__ void mma8(float4& d, const uint32_t a[4],
                                     uint32_t b0, uint32_t b1) {
    asm volatile(
        "mma.sync.aligned.m16n8k8.row.col.f32.tf32.tf32.f32 "
        "{%0,%1,%2,%3}, {%4,%5,%6,%7}, {%8,%9}, {%0,%1,%2,%3};"
        : "+f"(d.x), "+f"(d.y), "+f"(d.z), "+f"(d.w)
        : "r"(a[0]), "r"(a[1]), "r"(a[2]), "r"(a[3]), "r"(b0), "r"(b1));
}
__device__ __forceinline__ uint32_t tf32u(float x) {
    uint32_t u;
    asm("cvt.rna.tf32.f32 %0, %1;" : "=r"(u) : "f"(x));
    return u;
}
__device__ __forceinline__ float tf32f(float x) {
    return __uint_as_float(tf32u(x));
}

// ============================================================
// Kernel 1: patch-embed GEMM (fp32, small: 1.6 GF)
// ============================================================
__global__ __launch_bounds__(256) void patch_embed_kernel(
    const float* __restrict__ x, const float* __restrict__ w,
    const float* __restrict__ bias)
{
    __shared__ float As[16][64];
    __shared__ float Bs[16][64];
    const int tid = threadIdx.x;
    const int tx = tid & 15, ty = tid >> 4;
    const int m0 = blockIdx.y * 64;
    const int n0 = blockIdx.x * 64;
    const int lm = tid >> 2;
    const int lk = (tid & 3) * 4;
    const int tok = m0 + lm;
    const int pr = tok >> 6, pc = tok & 63;

    float acc[4][4];
#pragma unroll
    for (int i = 0; i < 4; i++)
#pragma unroll
        for (int j = 0; j < 4; j++) acc[i][j] = 0.f;

    for (int kt = 0; kt < KPATCH; kt += 16) {
        const int i = (kt + lk) >> 4;
        const int j = lk;
        float4 a4 = *(const float4*)&x[(pr * 16 + i) * 1024 + pc * 16 + j];
        As[lk + 0][lm] = a4.x; As[lk + 1][lm] = a4.y;
        As[lk + 2][lm] = a4.z; As[lk + 3][lm] = a4.w;
        float4 b4 = *(const float4*)&w[(n0 + lm) * KPATCH + kt + lk];
        Bs[lk + 0][lm] = b4.x; Bs[lk + 1][lm] = b4.y;
        Bs[lk + 2][lm] = b4.z; Bs[lk + 3][lm] = b4.w;
        __syncthreads();
#pragma unroll
        for (int kk = 0; kk < 16; kk++) {
            float4 av = *(const float4*)&As[kk][ty * 4];
            float4 bv = *(const float4*)&Bs[kk][tx * 4];
            float am[4] = {av.x, av.y, av.z, av.w};
            float bn[4] = {bv.x, bv.y, bv.z, bv.w};
#pragma unroll
            for (int i2 = 0; i2 < 4; i2++)
#pragma unroll
                for (int j2 = 0; j2 < 4; j2++) acc[i2][j2] += am[i2] * bn[j2];
        }
        __syncthreads();
    }
#pragma unroll
    for (int i = 0; i < 4; i++) {
        int m = m0 + ty * 4 + i;
#pragma unroll
        for (int j = 0; j < 4; j++) {
            int n = n0 + tx * 4 + j;
            g_tok[m * EMBED + n] = acc[i][j] + bias[n];
        }
    }
}

// ============================================================
// Kernel 2: LayerNorm; outputs rounded to tf32 for downstream mma
// ============================================================
__device__ __forceinline__ float block_sum256(float v) {
    __shared__ float sh[8];
    __syncthreads();
    const int lane = threadIdx.x & 31, wrp = threadIdx.x >> 5;
#pragma unroll
    for (int o = 16; o > 0; o >>= 1) v += __shfl_xor_sync(0xffffffffu, v, o);
    if (lane == 0) sh[wrp] = v;
    __syncthreads();
    if (wrp == 0) {
        v = (lane < 8) ? sh[lane] : 0.f;
#pragma unroll
        for (int o = 4; o > 0; o >>= 1) v += __shfl_xor_sync(0xffffffffu, v, o);
        if (lane == 0) sh[0] = v;
    }
    __syncthreads();
    return sh[0];
}

__global__ __launch_bounds__(256) void ln_kernel(
    const float* __restrict__ gamma, const float* __restrict__ beta)
{
    const int n = blockIdx.x;
    const int t = threadIdx.x;
    float* row = &g_tok[n * EMBED];
    float v0 = row[t], v1 = row[t + 256], v2 = row[t + 512];
    float total = block_sum256(v0 + v1 + v2);
    float mu = total * (1.f / EMBED);
    float d0 = v0 - mu, d1 = v1 - mu, d2 = v2 - mu;
    float tot2 = block_sum256(d0 * d0 + d1 * d1 + d2 * d2);
    float inv = rsqrtf(tot2 * (1.f / EMBED) + 1e-6f);
    row[t]       = tf32f(d0 * inv * gamma[t]       + beta[t]);
    row[t + 256] = tf32f(d1 * inv * gamma[t + 256] + beta[t + 256]);
    row[t + 512] = tf32f(d2 * inv * gamma[t + 512] + beta[t + 512]);
}

// ============================================================
// Kernel 3: QKV GEMM, tf32 mma.sync.  C[m,n] = sum_k tok[m,k] W[n,k]
// M=4096, N=2304, K=768.  CTA 128x128, k-tile 32, 8 warps (2m x 4n),
// warp tile 64x32.  cp.async double-buffered smem (pad 32->36 floats).
// ============================================================
#define GP 36
#define GTILE (128 * GP)
#define QKV_SMEM (4 * GTILE * 4)

__global__ __launch_bounds__(256, 2) void qkv_kernel(const float* __restrict__ w)
{
    extern __shared__ float sm[];
    float* ab[2] = { sm,             sm + GTILE };
    float* bb[2] = { sm + 2 * GTILE, sm + 3 * GTILE };
    const uint32_t ab_u[2] = { smem_u32(ab[0]), smem_u32(ab[1]) };
    const uint32_t bb_u[2] = { smem_u32(bb[0]), smem_u32(bb[1]) };

    const int tid = threadIdx.x, wid = tid >> 5, lane = tid & 31;
    const int lj = lane & 3, lr = lane >> 2;
    const int wm = wid >> 2, wn = wid & 3;
    const int m0 = blockIdx.y * 128, n0 = blockIdx.x * 128;

    float4 acc[4][4];
#pragma unroll
    for (int i = 0; i < 4; i++)
#pragma unroll
        for (int j = 0; j < 4; j++) acc[i][j] = make_float4(0.f, 0.f, 0.f, 0.f);

    // 1024 A-chunks + 1024 B-chunks, 16B each; 4+4 per thread
#define QKV_ISSUE(KT, B) do {                                                  \
    _Pragma("unroll")                                                          \
    for (int i = 0; i < 4; i++) {                                              \
        int c = tid + i * 256;                                                 \
        int r = c >> 3, cl = c & 7;                                            \
        cp16(ab_u[B] + (r * GP + cl * 4) * 4,                                  \
             g_tok + (m0 + r) * EMBED + (KT) + cl * 4);                        \
        cp16(bb_u[B] + (r * GP + cl * 4) * 4,                                  \
             w + (n0 + r) * EMBED + (KT) + cl * 4);                            \
    } } while (0)

    QKV_ISSUE(0, 0);  CP_COMMIT();
    QKV_ISSUE(32, 1); CP_COMMIT();

    const int NIT = EMBED / 32;   // 24
    for (int it = 0; it < NIT; it++) {
        const int b = it & 1;
        CP_WAIT1();
        __syncthreads();
        const float* A = ab[b];
        const float* B = bb[b];
#pragma unroll
        for (int g = 0; g < 4; g++) {
            uint32_t af[4][4];
#pragma unroll
            for (int mt = 0; mt < 4; mt++) {
                int r0 = wm * 64 + mt * 16 + lr;
                af[mt][0] = __float_as_uint(A[r0 * GP + g * 8 + lj]);
                af[mt][1] = __float_as_uint(A[(r0 + 8) * GP + g * 8 + lj]);
                af[mt][2] = __float_as_uint(A[r0 * GP + g * 8 + lj + 4]);
                af[mt][3] = __float_as_uint(A[(r0 + 8) * GP + g * 8 + lj + 4]);
            }
#pragma unroll
            for (int nt = 0; nt < 4; nt++) {
                int c0 = wn * 32 + nt * 8 + lr;
                uint32_t b0 = __float_as_uint(B[c0 * GP + g * 8 + lj]);
                uint32_t b1 = __float_as_uint(B[c0 * GP + g * 8 + lj + 4]);
#pragma unroll
                for (int mt = 0; mt < 4; mt++) mma8(acc[mt][nt], af[mt], b0, b1);
            }
        }
        __syncthreads();
        if (it + 2 < NIT) QKV_ISSUE((it + 2) * 32, b);
        CP_COMMIT();
    }

    // epilogue: scatter to q/k/v [h, n, d], rounded to tf32
#pragma unroll
    for (int nt = 0; nt < 4; nt++) {
        int n = n0 + wn * 32 + nt * 8 + 2 * lj;
        int s = n / EMBED;
        int r = n % EMBED;
        int hh = r / DHEAD, dd = r % DHEAD;
        float* dst = ((s == 0) ? g_q : (s == 1) ? g_k : g_v)
                   + (hh * N_TOK) * DHEAD + dd;
#pragma unroll
        for (int mt = 0; mt < 4; mt++) {
            int row = m0 + wm * 64 + mt * 16 + lr;
            float2 v0 = make_float2(tf32f(acc[mt][nt].x), tf32f(acc[mt][nt].y));
            float2 v8 = make_float2(tf32f(acc[mt][nt].z), tf32f(acc[mt][nt].w));
            *(float2*)(dst + row * DHEAD) = v0;
            *(float2*)(dst + (row + 8) * DHEAD) = v8;
        }
    }
}

// ============================================================
// Kernel 4: flash attention, tf32 mma.sync.
// CTA = (head, 128 queries), 8 warps, each warp owns a 16-row strip.
// Per kv tile (128): S = Q K^T in regs -> exp -> O += P V.
// PV uses kv-permutation sigma(k)=2k / 2k+1 so S-acc regs feed A-frags
// directly (order c0,c2,c1,c3) with V rows read at 2j / 2j+1.
// ============================================================
#define AQ   128
#define AKV  128
#define APAD 68
#define ATILE (AKV * APAD)
#define ATT_SMEM (4 * ATILE * 4)

__global__ __launch_bounds__(256, 1) void attn_kernel(float* __restrict__ out)
{
    extern __shared__ float sm[];
    float* kb[2] = { sm,             sm + ATILE };
    float* vb[2] = { sm + 2 * ATILE, sm + 3 * ATILE };
    const uint32_t kb_u[2] = { smem_u32(kb[0]), smem_u32(kb[1]) };
    const uint32_t vb_u[2] = { smem_u32(vb[0]), smem_u32(vb[1]) };

    const int tid = threadIdx.x, wid = tid >> 5, lane = tid & 31;
    const int lj = lane & 3, lr = lane >> 2;
    const int h = blockIdx.y, q0 = blockIdx.x * AQ;

    const float* Kh = g_k + h * N_TOK * DHEAD;
    const float* Vh = g_v + h * N_TOK * DHEAD;

    // Q fragments (q/k/v already tf32-rounded by qkv epilogue)
    uint32_t qa[8][4];
    {
        const float* Q0 = g_q + (h * N_TOK + q0 + wid * 16 + lr) * DHEAD;
        const float* Q8 = Q0 + 8 * DHEAD;
#pragma unroll
        for (int g = 0; g < 8; g++) {
            qa[g][0] = __float_as_uint(Q0[8 * g + lj]);
            qa[g][1] = __float_as_uint(Q8[8 * g + lj]);
            qa[g][2] = __float_as_uint(Q0[8 * g + lj + 4]);
            qa[g][3] = __float_as_uint(Q8[8 * g + lj + 4]);
        }
    }

    float4 oacc[8];
#pragma unroll
    for (int i = 0; i < 8; i++) oacc[i] = make_float4(0.f, 0.f, 0.f, 0.f);
    float l_lo = 0.f, l_hi = 0.f;

    // K tile = 128 rows x 64 floats = 2048 16B-chunks; same for V.
    // 8 K-chunks + 8 V-chunks per thread.
#define ATT_ISSUE(T, B) do {                                                   \
    _Pragma("unroll")                                                          \
    for (int i = 0; i < 8; i++) {                                              \
        int c = tid + i * 256;                                                 \
        int r = c >> 4, cl = c & 15;                                           \
        cp16(kb_u[B] + (r * APAD + cl * 4) * 4,                                \
             Kh + ((T) * AKV + r) * DHEAD + cl * 4);                           \
        cp16(vb_u[B] + (r * APAD + cl * 4) * 4,                                \
             Vh + ((T) * AKV + r) * DHEAD + cl * 4);                           \
    } } while (0)

    ATT_ISSUE(0, 0); CP_COMMIT();
    ATT_ISSUE(1, 1); CP_COMMIT();

    const int NT = N_TOK / AKV;   // 32
    for (int t = 0; t < NT; t++) {
        const int b = t & 1;
        CP_WAIT1();
        __syncthreads();
        const float* K = kb[b];
        const float* V = vb[b];

        // ---- S = Q K^T : 16 n-tiles of 8 kv ----
        float4 sacc[16];
#pragma unroll
        for (int nt = 0; nt < 16; nt++) sacc[nt] = make_float4(0.f, 0.f, 0.f, 0.f);
#pragma unroll
        for (int g = 0; g < 8; g++) {
#pragma unroll
            for (int nt = 0; nt < 16; nt++) {
                const float* kp = K + (nt * 8 + lr) * APAD + g * 8 + lj;
                uint32_t b0 = __float_as_uint(kp[0]);
                uint32_t b1 = __float_as_uint(kp[4]);
                mma8(sacc[nt], qa[g], b0, b1);
            }
        }

        // ---- exp + O += P V ----
#pragma unroll
        for (int g = 0; g < 16; g++) {
            float p0 = __expf(sacc[g].x * 0.125f);
            float p1 = __expf(sacc[g].y * 0.125f);
            float p2 = __expf(sacc[g].z * 0.125f);
            float p3 = __expf(sacc[g].w * 0.125f);
            l_lo += p0 + p1;
            l_hi += p2 + p3;
            uint32_t pa[4] = { tf32u(p0), tf32u(p2), tf32u(p1), tf32u(p3) };
            const float* v0p = V + (8 * g + 2 * lj) * APAD + lr;
            const float* v1p = v0p + APAD;
#pragma unroll
            for (int dt = 0; dt < 8; dt++) {
                uint32_t b0 = __float_as_uint(v0p[dt * 8]);
                uint32_t b1 = __float_as_uint(v1p[dt * 8]);
                mma8(oacc[dt], pa, b0, b1);
            }
        }

        __syncthreads();
        if (t + 2 < NT) ATT_ISSUE(t + 2, b);
        CP_COMMIT();
    }

    // ---- epilogue: quad-reduce l, normalize, store ----
    l_lo += __shfl_xor_sync(0xffffffffu, l_lo, 1);
    l_lo += __shfl_xor_sync(0xffffffffu, l_lo, 2);
    l_hi += __shfl_xor_sync(0xffffffffu, l_hi, 1);
    l_hi += __shfl_xor_sync(0xffffffffu, l_hi, 2);
    const float inv_lo = 1.f / l_lo;
    const float inv_hi = 1.f / l_hi;
    const int row = q0 + wid * 16 + lr;
    float* o0 = out + row * EMBED + h * DHEAD + 2 * lj;
    float* o8 = o0 + 8 * EMBED;
#pragma unroll
    for (int dt = 0; dt < 8; dt++) {
        *(float2*)(o0 + dt * 8) = make_float2(oacc[dt].x * inv_lo,
                                              oacc[dt].y * inv_lo);
        *(float2*)(o8 + dt * 8) = make_float2(oacc[dt].z * inv_hi,
                                              oacc[dt].w * inv_hi);
    }
}

// ============================================================
extern "C" void kernel_launch(void* const* d_in, const int* in_sizes, int n_in,
                              void* d_out, int out_size)
{
    const float* x  = (const float*)d_in[0];
    const float* pw = (const float*)d_in[1];
    const float* pb = (const float*)d_in[2];
    const float* lg = (const float*)d_in[3];
    const float* lb = (const float*)d_in[4];
    const float* qw = (const float*)d_in[5];
    float* out = (float*)d_out;

    cudaFuncSetAttribute(qkv_kernel,
                         cudaFuncAttributeMaxDynamicSharedMemorySize, QKV_SMEM);
    cudaFuncSetAttribute(attn_kernel,
                         cudaFuncAttributeMaxDynamicSharedMemorySize, ATT_SMEM);

    patch_embed_kernel<<<dim3(EMBED / 64, N_TOK / 64), 256>>>(x, pw, pb);
    ln_kernel<<<N_TOK, 256>>>(lg, lb);
    qkv_kernel<<<dim3(2304 / 128, N_TOK / 128), 256, QKV_SMEM>>>(qw);
    attn_kernel<<<dim3(N_TOK / AQ, NHEAD), 256, ATT_SMEM>>>(out);
}